// round 2
// baseline (speedup 1.0000x reference)
#include <cuda_runtime.h>

#define NN 100000
#define NE 1600000
#define CH 64
#define NG 64
#define SCAN_BS 1024
#define SCAN_NB ((NN + SCAN_BS - 1) / SCAN_BS)   // 98

// ---------------- device scratch (no allocation allowed) ----------------
__device__ __align__(16) float g_agg[NN * CH];
__device__ __align__(16) float g_h0[NN * CH];
__device__ __align__(16) float g_h1[NN * CH];
__device__ float g_inv[NN];
__device__ int   g_deg[NN];
__device__ int   g_off[NN];
__device__ int   g_fill[NN];
__device__ int   g_srcl[NE];
__device__ int   g_bsum[SCAN_NB];
__device__ int   g_bpre[SCAN_NB];
__device__ float g_pool[NG * CH];
__device__ float g_pcnt[NG];
__device__ int   g_is64_ei;
__device__ int   g_is64_b;

// ---------------- dtype detection ----------------
// int64 little-endian with values < 2^31 => all odd 32-bit words are zero.
__global__ void detect_kernel(const int* __restrict__ ei32,
                              const int* __restrict__ b32) {
    if (threadIdx.x == 0 && blockIdx.x == 0) {
        int or_ei = 0;
        for (int i = 0; i < 64; i++) {
            int pos = 2 * (i * 24999 + 7) + 1;   // < 3.2M even if int32
            or_ei |= ei32[pos];
        }
        int or_b = 0;
        for (int i = 0; i < 64; i++) {
            int pos = 2 * (i * 780 + 3) + 1;     // < 100000 even if int32
            or_b |= b32[pos];
        }
        g_is64_ei = (or_ei == 0) ? 1 : 0;
        g_is64_b  = (or_b  == 0) ? 1 : 0;
    }
}

// ---------------- zero kernels ----------------
__global__ void zero_build_kernel() {
    int i = blockIdx.x * blockDim.x + threadIdx.x;
    if (i < NN) { g_deg[i] = 0; g_fill[i] = 0; }
}
__global__ void zero_pool_kernel() {
    int i = threadIdx.x;
    for (int j = i; j < NG * CH; j += blockDim.x) g_pool[j] = 0.f;
    if (i < NG) g_pcnt[i] = 0.f;
}

// ---------------- CSR build ----------------
__global__ void deg_kernel(const int* __restrict__ ei) {
    int e = blockIdx.x * blockDim.x + threadIdx.x;
    if (e < NE) {
        int is64 = g_is64_ei;
        int d = is64 ? ei[2 * (NE + e)] : ei[NE + e];
        atomicAdd(&g_deg[d], 1);
    }
}
__global__ void inv_kernel() {
    int i = blockIdx.x * blockDim.x + threadIdx.x;
    if (i < NN) g_inv[i] = 1.0f / fmaxf((float)g_deg[i], 1.0f);
}
__global__ void scan1_kernel() {
    __shared__ int s[SCAN_BS];
    int t = threadIdx.x;
    int gid = blockIdx.x * SCAN_BS + t;
    int v = (gid < NN) ? g_deg[gid] : 0;
    s[t] = v;
    __syncthreads();
    for (int off = 1; off < SCAN_BS; off <<= 1) {
        int x = (t >= off) ? s[t - off] : 0;
        __syncthreads();
        s[t] += x;
        __syncthreads();
    }
    if (gid < NN) g_off[gid] = s[t] - v;        // exclusive within block
    if (t == SCAN_BS - 1) g_bsum[blockIdx.x] = s[t];
}
__global__ void scan2_kernel() {
    if (threadIdx.x == 0 && blockIdx.x == 0) {
        int acc = 0;
        for (int i = 0; i < SCAN_NB; i++) { g_bpre[i] = acc; acc += g_bsum[i]; }
    }
}
__global__ void scan3_kernel() {
    int gid = blockIdx.x * SCAN_BS + threadIdx.x;
    if (gid < NN) g_off[gid] += g_bpre[blockIdx.x];
}
__global__ void fill_kernel(const int* __restrict__ ei) {
    int e = blockIdx.x * blockDim.x + threadIdx.x;
    if (e < NE) {
        int is64 = g_is64_ei;
        int s = is64 ? ei[2 * e]        : ei[e];
        int d = is64 ? ei[2 * (NE + e)] : ei[NE + e];
        int pos = g_off[d] + atomicAdd(&g_fill[d], 1);
        g_srcl[pos] = s;
    }
}

// ---------------- aggregation via gather (no atomics) ----------------
// warp per dst node; lane owns channels lane and lane+32. Fuses mean (inv).
__global__ void __launch_bounds__(256) gather_kernel(const float* __restrict__ Xext,
                                                     int srcsel) {
    const float* X = (srcsel == 0) ? Xext : (srcsel == 1 ? g_h0 : g_h1);
    int warp = (blockIdx.x * blockDim.x + threadIdx.x) >> 5;
    int lane = threadIdx.x & 31;
    if (warp >= NN) return;
    int beg = g_off[warp];
    int deg = g_deg[warp];
    float a0 = 0.f, a1 = 0.f;
    int j = 0;
    for (; j + 2 <= deg; j += 2) {
        int s0 = g_srcl[beg + j];
        int s1 = g_srcl[beg + j + 1];
        const float* r0 = X + (size_t)s0 * CH;
        const float* r1 = X + (size_t)s1 * CH;
        float v0 = r0[lane], v1 = r0[lane + 32];
        float u0 = r1[lane], u1 = r1[lane + 32];
        a0 += v0 + u0;
        a1 += v1 + u1;
    }
    if (j < deg) {
        int s0 = g_srcl[beg + j];
        const float* r0 = X + (size_t)s0 * CH;
        a0 += r0[lane];
        a1 += r0[lane + 32];
    }
    float iv = g_inv[warp];
    g_agg[(size_t)warp * CH + lane]      = a0 * iv;
    g_agg[(size_t)warp * CH + lane + 32] = a1 * iv;
}

// ---------------- node transform: Y = relu([agg | X] @ [Wl;Wr] + b) ----------------
// 64-node tile, 256 threads, 4x4 micro-tile, k-chunked A in shared (41.5KB total).
__global__ void __launch_bounds__(256) node_kernel(const float* __restrict__ Xext,
                                                   const float* __restrict__ Wl,
                                                   const float* __restrict__ bvec,
                                                   const float* __restrict__ Wr,
                                                   int srcsel, int dstsel) {
    const float* Xin = (srcsel == 0) ? Xext : (srcsel == 1 ? g_h0 : g_h1);
    float* Yout = (dstsel == 1) ? g_h0 : g_h1;

    __shared__ float Ws[128][64];   // rows 0..63 = Wl, 64..127 = Wr (32 KB)
    __shared__ float Ac[64][33];    // 64-node x 32-k chunk (8.4 KB)
    __shared__ float bs[64];

    int tid = threadIdx.x;
    int nbase = blockIdx.x * 64;

    for (int i = tid; i < 64 * 64; i += 256) {
        int k = i >> 6, j = i & 63;
        Ws[k][j]      = Wl[i];
        Ws[k + 64][j] = Wr[i];
    }
    if (tid < 64) bs[tid] = bvec[tid];

    int tx = tid & 15;   // output cols 4*tx..4*tx+3
    int ty = tid >> 4;   // rows 4*ty..4*ty+3

    float acc[4][4];
#pragma unroll
    for (int i = 0; i < 4; i++)
#pragma unroll
        for (int j = 0; j < 4; j++) acc[i][j] = 0.f;

    for (int c = 0; c < 4; c++) {
        __syncthreads();
        {
            int k = tid & 31;
            int n0 = tid >> 5;
            const float* Sbase = (c < 2) ? g_agg : Xin;
            int koff = (c & 1) * 32;
#pragma unroll
            for (int nn = n0; nn < 64; nn += 8) {
                int n = nbase + nn;
                Ac[nn][k] = (n < NN) ? Sbase[(size_t)n * CH + koff + k] : 0.f;
            }
        }
        __syncthreads();
        int kb = c * 32;
#pragma unroll
        for (int kk = 0; kk < 32; kk++) {
            float4 w = *(const float4*)&Ws[kb + kk][tx * 4];
#pragma unroll
            for (int i = 0; i < 4; i++) {
                float a = Ac[ty * 4 + i][kk];
                acc[i][0] += a * w.x;
                acc[i][1] += a * w.y;
                acc[i][2] += a * w.z;
                acc[i][3] += a * w.w;
            }
        }
    }

#pragma unroll
    for (int i = 0; i < 4; i++) {
        int n = nbase + ty * 4 + i;
        if (n < NN) {
            float4 o;
            o.x = fmaxf(acc[i][0] + bs[tx * 4 + 0], 0.f);
            o.y = fmaxf(acc[i][1] + bs[tx * 4 + 1], 0.f);
            o.z = fmaxf(acc[i][2] + bs[tx * 4 + 2], 0.f);
            o.w = fmaxf(acc[i][3] + bs[tx * 4 + 3], 0.f);
            *(float4*)&Yout[(size_t)n * CH + tx * 4] = o;
        }
    }
}

// ---------------- pooling (batch is sorted) ----------------
__global__ void __launch_bounds__(256) pool_kernel(const int* __restrict__ batch) {
    int is64 = g_is64_b;
    const float* H = g_h0;   // final layer output lives in g_h0
    int c = threadIdx.x & 63;
    int rg = threadIdx.x >> 6;
    int r0 = blockIdx.x * 256 + rg * 64;
    float acc = 0.f, cacc = 0.f;
    int cur = -1;
    for (int i = 0; i < 64; i++) {
        int r = r0 + i;
        if (r >= NN) break;
        int g = is64 ? batch[2 * r] : batch[r];
        if (g != cur) {
            if (cur >= 0) {
                atomicAdd(&g_pool[cur * CH + c], acc);
                if (c == 0) atomicAdd(&g_pcnt[cur], cacc);
            }
            cur = g; acc = 0.f; cacc = 0.f;
        }
        acc += H[(size_t)r * CH + c];
        cacc += 1.f;
    }
    if (cur >= 0) {
        atomicAdd(&g_pool[cur * CH + c], acc);
        if (c == 0) atomicAdd(&g_pcnt[cur], cacc);
    }
}

// ---------------- MLP head ----------------
__global__ void head_kernel(const float* __restrict__ Wc1, const float* __restrict__ bc1,
                            const float* __restrict__ Wc2, const float* __restrict__ bc2,
                            float* __restrict__ out) {
    int g = threadIdx.x;
    if (g >= NG) return;
    float iv = 1.0f / fmaxf(g_pcnt[g], 1.0f);
    float gv[64];
#pragma unroll
    for (int k = 0; k < 64; k++) gv[k] = g_pool[g * CH + k] * iv;
    float o0 = bc2[0], o1 = bc2[1];
    for (int j = 0; j < 32; j++) {
        float h = bc1[j];
#pragma unroll
        for (int k = 0; k < 64; k++) h += gv[k] * Wc1[k * 32 + j];
        h = fmaxf(h, 0.f);
        o0 += h * Wc2[j * 2 + 0];
        o1 += h * Wc2[j * 2 + 1];
    }
    out[g * 2 + 0] = o0;
    out[g * 2 + 1] = o1;
}

extern "C" void kernel_launch(void* const* d_in, const int* in_sizes, int n_in,
                              void* d_out, int out_size) {
    (void)in_sizes; (void)n_in; (void)out_size;
    const float* x   = (const float*)d_in[0];
    const int* ei    = (const int*)d_in[1];    // width auto-detected on device
    const int* batch = (const int*)d_in[2];
    const float* W1l = (const float*)d_in[3];
    const float* b1  = (const float*)d_in[4];
    const float* W1r = (const float*)d_in[5];
    const float* W2l = (const float*)d_in[6];
    const float* b2  = (const float*)d_in[7];
    const float* W2r = (const float*)d_in[8];
    const float* W3l = (const float*)d_in[9];
    const float* b3  = (const float*)d_in[10];
    const float* W3r = (const float*)d_in[11];
    const float* Wc1 = (const float*)d_in[12];
    const float* bc1 = (const float*)d_in[13];
    const float* Wc2 = (const float*)d_in[14];
    const float* bc2 = (const float*)d_in[15];
    float* out = (float*)d_out;

    const int ZB = 256;
    const int gather_blocks = (NN + 7) / 8;      // 8 warps/block, warp per node
    const int node_blocks   = (NN + 63) / 64;

    detect_kernel<<<1, 32>>>(ei, batch);

    // CSR build
    zero_build_kernel<<<(NN + ZB - 1) / ZB, ZB>>>();
    deg_kernel<<<(NE + ZB - 1) / ZB, ZB>>>(ei);
    inv_kernel<<<(NN + ZB - 1) / ZB, ZB>>>();
    scan1_kernel<<<SCAN_NB, SCAN_BS>>>();
    scan2_kernel<<<1, 32>>>();
    scan3_kernel<<<SCAN_NB, SCAN_BS>>>();
    fill_kernel<<<(NE + ZB - 1) / ZB, ZB>>>(ei);

    // layer 1: x -> h0
    gather_kernel<<<gather_blocks, 256>>>(x, 0);
    node_kernel<<<node_blocks, 256>>>(x, W1l, b1, W1r, 0, 1);
    // layer 2: h0 -> h1
    gather_kernel<<<gather_blocks, 256>>>(x, 1);
    node_kernel<<<node_blocks, 256>>>(x, W2l, b2, W2r, 1, 2);
    // layer 3: h1 -> h0
    gather_kernel<<<gather_blocks, 256>>>(x, 2);
    node_kernel<<<node_blocks, 256>>>(x, W3l, b3, W3r, 2, 1);

    // pool + head
    zero_pool_kernel<<<1, 256>>>();
    pool_kernel<<<(NN + 255) / 256, 256>>>(batch);
    head_kernel<<<1, 64>>>(Wc1, bc1, Wc2, bc2, out);
}